// round 12
// baseline (speedup 1.0000x reference)
#include <cuda_runtime.h>
#include <cuda_fp16.h>

#define N_NODES 50000
#define E_EDGES 1600000
#define IN_DIM  128
#define OUT_DIM 128   // H*D = 8*16
#define H_HEADS 8

#define GEMM_BLOCKS_X ((N_NODES + 127) / 128)          // 391
#define GEMM_BLOCKS   (GEMM_BLOCKS_X * 3)              // 1173
#define HIST_BLOCKS   ((E_EDGES / 4 + 255) / 256)      // 1563

// ---------------- scratch (static device globals: allowed) ----------------
__device__ __align__(16) __half g_Qh[N_NODES * OUT_DIM];
// interleaved K/V: per node 256 halfs; chunk j (j=0..31): [k4j..k4j+3, v4j..v4j+3]
__device__ __align__(16) __half g_KVh[N_NODES * OUT_DIM * 2];
__device__ int g_cnt[N_NODES];          // zero-init at load; re-zeroed by scan each call
__device__ int g_rowptr[N_NODES + 1];
__device__ int g_rank[E_EDGES];
__device__ int g_esrc[E_EDGES];

// ---------------- tensor-core GEMM helpers ----------------
#define GK 64                 // k-half width
#define AS_LD 72              // (GK+8) halfs per A row
#define WS_LD 136             // (128+8) halfs per W row

__device__ __forceinline__ void ldsm_x4(unsigned& r0, unsigned& r1, unsigned& r2, unsigned& r3,
                                        const __half* p) {
    unsigned addr = (unsigned)__cvta_generic_to_shared(p);
    asm volatile("ldmatrix.sync.aligned.m8n8.x4.shared.b16 {%0,%1,%2,%3}, [%4];"
                 : "=r"(r0), "=r"(r1), "=r"(r2), "=r"(r3) : "r"(addr));
}
__device__ __forceinline__ void ldsm_x4_t(unsigned& r0, unsigned& r1, unsigned& r2, unsigned& r3,
                                          const __half* p) {
    unsigned addr = (unsigned)__cvta_generic_to_shared(p);
    asm volatile("ldmatrix.sync.aligned.m8n8.x4.trans.shared.b16 {%0,%1,%2,%3}, [%4];"
                 : "=r"(r0), "=r"(r1), "=r"(r2), "=r"(r3) : "r"(addr));
}
__device__ __forceinline__ void mma16816(float* c, const unsigned* a, const unsigned* b) {
    asm volatile(
        "mma.sync.aligned.m16n8k16.row.col.f32.f16.f16.f32 "
        "{%0,%1,%2,%3}, {%4,%5,%6,%7}, {%8,%9}, {%0,%1,%2,%3};"
        : "+f"(c[0]), "+f"(c[1]), "+f"(c[2]), "+f"(c[3])
        : "r"(a[0]), "r"(a[1]), "r"(a[2]), "r"(a[3]), "r"(b[0]), "r"(b[1]));
}

// ---------------- fused: QKV GEMM (blocks [0,GEMM_BLOCKS)) + hist (rest) ----
__global__ __launch_bounds__(256) void gemm_hist_kernel(
    const float* __restrict__ hin,
    const float* __restrict__ WQ, const float* __restrict__ WK, const float* __restrict__ WV,
    const float* __restrict__ bQ, const float* __restrict__ bK, const float* __restrict__ bV,
    const int* __restrict__ dst)
{
    __shared__ __half As[128 * AS_LD];
    __shared__ __half Ws[GK * WS_LD];

    const int t = threadIdx.x;

    if (blockIdx.x >= GEMM_BLOCKS) {
        // ---- histogram branch: 4 edges/thread, record rank ----
        int i = (blockIdx.x - GEMM_BLOCKS) * 256 + t;
        if (i < E_EDGES / 4) {
            int4 d = reinterpret_cast<const int4*>(dst)[i];
            int r0 = atomicAdd(&g_cnt[d.x], 1);
            int r1 = atomicAdd(&g_cnt[d.y], 1);
            int r2 = atomicAdd(&g_cnt[d.z], 1);
            int r3 = atomicAdd(&g_cnt[d.w], 1);
            reinterpret_cast<int4*>(g_rank)[i] = make_int4(r0, r1, r2, r3);
        }
        return;
    }

    // ---- GEMM branch ----
    const int bx = blockIdx.x % GEMM_BLOCKS_X;
    const int by = blockIdx.x / GEMM_BLOCKS_X;

    const float* W;
    const float* bias;
    if (by == 0)      { W = WQ; bias = bQ; }
    else if (by == 1) { W = WK; bias = bK; }
    else              { W = WV; bias = bV; }

    const int lane   = t & 31;
    const int wid    = t >> 5;
    const int warp_m = wid >> 1;
    const int warp_n = wid & 1;
    const int row0   = bx * 128;

    float acc[2][8][4];
#pragma unroll
    for (int i = 0; i < 2; i++)
#pragma unroll
        for (int j = 0; j < 8; j++)
#pragma unroll
            for (int c = 0; c < 4; c++) acc[i][j][c] = 0.f;

    for (int kt = 0; kt < IN_DIM; kt += GK) {
#pragma unroll
        for (int i = 0; i < 8; i++) {
            int idx = t + i * 256;
            int r   = idx >> 4;
            int c4  = idx & 15;
            int row = row0 + r;
            float4 v = make_float4(0.f, 0.f, 0.f, 0.f);
            if (row < N_NODES)
                v = *reinterpret_cast<const float4*>(&hin[(size_t)row * IN_DIM + kt + c4 * 4]);
            __half2 h0 = __floats2half2_rn(v.x, v.y);
            __half2 h1 = __floats2half2_rn(v.z, v.w);
            *reinterpret_cast<__half2*>(&As[r * AS_LD + c4 * 4])     = h0;
            *reinterpret_cast<__half2*>(&As[r * AS_LD + c4 * 4 + 2]) = h1;
        }
#pragma unroll
        for (int i = 0; i < 8; i++) {
            int idx = t + i * 256;
            int k   = idx >> 5;
            int c4  = idx & 31;
            float4 v = *reinterpret_cast<const float4*>(&W[(size_t)(kt + k) * OUT_DIM + c4 * 4]);
            __half2 h0 = __floats2half2_rn(v.x, v.y);
            __half2 h1 = __floats2half2_rn(v.z, v.w);
            *reinterpret_cast<__half2*>(&Ws[k * WS_LD + c4 * 4])     = h0;
            *reinterpret_cast<__half2*>(&Ws[k * WS_LD + c4 * 4 + 2]) = h1;
        }
        __syncthreads();

#pragma unroll
        for (int kk = 0; kk < GK; kk += 16) {
            unsigned a[2][4];
#pragma unroll
            for (int i = 0; i < 2; i++) {
                int r = warp_m * 32 + i * 16 + (lane & 15);
                int c = kk + 8 * (lane >> 4);
                ldsm_x4(a[i][0], a[i][1], a[i][2], a[i][3], &As[r * AS_LD + c]);
            }
            unsigned b[4][4];
#pragma unroll
            for (int j = 0; j < 4; j++) {
                int kr = kk + (lane & 15);
                int c  = warp_n * 64 + j * 16 + 8 * (lane >> 4);
                ldsm_x4_t(b[j][0], b[j][1], b[j][2], b[j][3], &Ws[kr * WS_LD + c]);
            }
#pragma unroll
            for (int i = 0; i < 2; i++)
#pragma unroll
                for (int j2 = 0; j2 < 8; j2++)
                    mma16816(acc[i][j2], a[i], &b[j2 >> 1][(j2 & 1) * 2]);
        }
        __syncthreads();
    }

    // epilogue: +bias, fp16; Q -> g_Qh; K/V -> interleaved g_KVh
    const int kv_off = (by == 2) ? 4 : 0;
#pragma unroll
    for (int i = 0; i < 2; i++) {
        int row_a = row0 + warp_m * 32 + i * 16 + (lane >> 2);
        int row_b = row_a + 8;
#pragma unroll
        for (int j2 = 0; j2 < 8; j2++) {
            int col = warp_n * 64 + j2 * 8 + (lane & 3) * 2;
            float b0 = __ldg(&bias[col]);
            float b1 = __ldg(&bias[col + 1]);
            __half2 oa = __floats2half2_rn(acc[i][j2][0] + b0, acc[i][j2][1] + b1);
            __half2 ob = __floats2half2_rn(acc[i][j2][2] + b0, acc[i][j2][3] + b1);
            if (by == 0) {
                if (row_a < N_NODES)
                    *reinterpret_cast<__half2*>(&g_Qh[(size_t)row_a * OUT_DIM + col]) = oa;
                if (row_b < N_NODES)
                    *reinterpret_cast<__half2*>(&g_Qh[(size_t)row_b * OUT_DIM + col]) = ob;
            } else {
                size_t off = (size_t)(col >> 2) * 8 + kv_off + (col & 3);
                if (row_a < N_NODES)
                    *reinterpret_cast<__half2*>(&g_KVh[(size_t)row_a * OUT_DIM * 2 + off]) = oa;
                if (row_b < N_NODES)
                    *reinterpret_cast<__half2*>(&g_KVh[(size_t)row_b * OUT_DIM * 2 + off]) = ob;
            }
        }
    }
}

// ---------------- scan (rowptr; also re-zeroes g_cnt for next call) --------
__global__ __launch_bounds__(1024) void scan_kernel() {
    __shared__ int sums[1024];
    const int CH = 52;                       // 1024*52 >= 50000, 52 % 4 == 0
    const int t = threadIdx.x;
    const int base = t * CH;
    int s = 0;
    for (int i = 0; i < CH; i += 4) {
        int idx = base + i;
        if (idx + 3 < N_NODES) {
            int4 c = *reinterpret_cast<const int4*>(&g_cnt[idx]);
            s += c.x + c.y + c.z + c.w;
        } else {
            for (int j = 0; j < 4; j++)
                if (idx + j < N_NODES) s += g_cnt[idx + j];
        }
    }
    sums[t] = s;
    __syncthreads();
    for (int off = 1; off < 1024; off <<= 1) {
        int v = (t >= off) ? sums[t - off] : 0;
        __syncthreads();
        sums[t] += v;
        __syncthreads();
    }
    int run = sums[t] - s;
    for (int i = 0; i < CH; i++) {
        int idx = base + i;
        if (idx < N_NODES) {
            int c = g_cnt[idx];
            g_rowptr[idx] = run;
            run += c;
            g_cnt[idx] = 0;          // fold zero_cnt into the last reader
        }
    }
    if (t == 0) g_rowptr[N_NODES] = E_EDGES;
}

// ---------------- atomic-free scatter using precomputed ranks (4/thread) ----
__global__ void scatter_kernel(const int* __restrict__ src, const int* __restrict__ dst) {
    int i = blockIdx.x * blockDim.x + threadIdx.x;   // < E/4
    if (i < E_EDGES / 4) {
        int4 d = reinterpret_cast<const int4*>(dst)[i];
        int4 s = reinterpret_cast<const int4*>(src)[i];
        int4 r = reinterpret_cast<const int4*>(g_rank)[i];
        g_esrc[__ldg(&g_rowptr[d.x]) + r.x] = s.x;
        g_esrc[__ldg(&g_rowptr[d.y]) + r.y] = s.y;
        g_esrc[__ldg(&g_rowptr[d.z]) + r.z] = s.z;
        g_esrc[__ldg(&g_rowptr[d.w]) + r.w] = s.w;
    }
}

// ---------------- gather: warp per dst node ---------------------------------
// Unmasked 8-wide main loop + ONE masked tail group (no serial tail).
struct F4 { float x, y, z, w; };

__device__ __forceinline__ F4 cvt2(unsigned lo, unsigned hi) {
    __half2 h0 = *reinterpret_cast<__half2*>(&lo);
    __half2 h1 = *reinterpret_cast<__half2*>(&hi);
    float2 f0 = __half22float2(h0);
    float2 f1 = __half22float2(h1);
    F4 r; r.x = f0.x; r.y = f0.y; r.z = f1.x; r.w = f1.y;
    return r;
}

__device__ __forceinline__ float edge_score(const F4& kv, const F4& qv) {
    float p = kv.x * qv.x + kv.y * qv.y + kv.z * qv.z + kv.w * qv.w;
    p += __shfl_xor_sync(0xFFFFFFFFu, p, 1);
    p += __shfl_xor_sync(0xFFFFFFFFu, p, 2);
    return __expf(fminf(fmaxf(p * 0.25f, -5.f), 5.f));
}

__global__ __launch_bounds__(256) void gather_kernel(float* __restrict__ out) {
    const int node = (blockIdx.x * blockDim.x + threadIdx.x) >> 5;
    if (node >= N_NODES) return;
    const int lane = threadIdx.x & 31;
    const unsigned lane8 = lane * 8;

    const uint2 qraw = *reinterpret_cast<const uint2*>(&g_Qh[(size_t)node * OUT_DIM + lane * 4]);
    const F4 qv = cvt2(qraw.x, qraw.y);
    const int beg = __ldg(&g_rowptr[node]);
    const int end = __ldg(&g_rowptr[node + 1]);

    float ax = 0.f, ay = 0.f, az = 0.f, aw = 0.f, z = 0.f;

    // unmasked full 8-groups
    int i = beg;
    const int full_end = beg + ((end - beg) & ~7);
    for (; i < full_end; i += 8) {
        int s[8];
#pragma unroll
        for (int j = 0; j < 8; j++) s[j] = __ldg(&g_esrc[i + j]);
        uint4 kv[8];
#pragma unroll
        for (int j = 0; j < 8; j++)
            kv[j] = *reinterpret_cast<const uint4*>(&g_KVh[(size_t)s[j] * (OUT_DIM * 2) + lane8]);
#pragma unroll
        for (int j = 0; j < 8; j++) {
            F4 k = cvt2(kv[j].x, kv[j].y);
            float sc = edge_score(k, qv);
            F4 v = cvt2(kv[j].z, kv[j].w);
            ax = fmaf(sc, v.x, ax); ay = fmaf(sc, v.y, ay);
            az = fmaf(sc, v.z, az); aw = fmaf(sc, v.w, aw);
            z += sc;
        }
    }

    // one masked tail group (lim in 1..7), loads clamped to a valid edge
    if (i < end) {
        const int lim = end - i;
        int s[8];
#pragma unroll
        for (int j = 0; j < 8; j++) {
            int e = i + j;
            s[j] = __ldg(&g_esrc[(e < end) ? e : (end - 1)]);
        }
        uint4 kv[8];
#pragma unroll
        for (int j = 0; j < 8; j++)
            kv[j] = *reinterpret_cast<const uint4*>(&g_KVh[(size_t)s[j] * (OUT_DIM * 2) + lane8]);
#pragma unroll
        for (int j = 0; j < 8; j++) {
            F4 k = cvt2(kv[j].x, kv[j].y);
            float sc = edge_score(k, qv);
            sc = (j < lim) ? sc : 0.f;
            F4 v = cvt2(kv[j].z, kv[j].w);
            ax = fmaf(sc, v.x, ax); ay = fmaf(sc, v.y, ay);
            az = fmaf(sc, v.z, az); aw = fmaf(sc, v.w, aw);
            z += sc;
        }
    }

    const float inv = 1.0f / z;
    float4 o = make_float4(ax * inv, ay * inv, az * inv, aw * inv);
    *reinterpret_cast<float4*>(&out[(size_t)node * OUT_DIM + lane * 4]) = o;
}

// ---------------- launch ----------------
extern "C" void kernel_launch(void* const* d_in, const int* in_sizes, int n_in,
                              void* d_out, int out_size)
{
    const float* h   = (const float*)d_in[0];
    const int*   src = (const int*)  d_in[1];
    const int*   dst = (const int*)  d_in[2];
    const float* WQ  = (const float*)d_in[3];
    const float* WK  = (const float*)d_in[4];
    const float* WV  = (const float*)d_in[5];
    const float* bQ  = (const float*)d_in[6];
    const float* bK  = (const float*)d_in[7];
    const float* bV  = (const float*)d_in[8];
    float* out = (float*)d_out;

    (void)in_sizes; (void)n_in; (void)out_size;

    // 1) fused QKV GEMM + histogram (g_cnt pre-zeroed by previous scan / static init)
    gemm_hist_kernel<<<GEMM_BLOCKS + HIST_BLOCKS, 256>>>(h, WQ, WK, WV, bQ, bK, bV, dst);

    // 2) rowptr scan (+ re-zero counts for next call)
    scan_kernel<<<1, 1024>>>();

    // 3) atomic-free scatter via ranks (4 edges/thread)
    scatter_kernel<<<(E_EDGES / 4 + 255) / 256, 256>>>(src, dst);

    // 4) warp-per-node gather + fused normalize
    gather_kernel<<<(N_NODES * 32 + 255) / 256, 256>>>(out);
}

// round 13
// speedup vs baseline: 1.5379x; 1.5379x over previous
#include <cuda_runtime.h>
#include <cuda_fp16.h>

#define N_NODES 50000
#define E_EDGES 1600000
#define IN_DIM  128
#define OUT_DIM 128   // H*D = 8*16
#define H_HEADS 8

#define GEMM_BLOCKS_X ((N_NODES + 127) / 128)          // 391
#define GEMM_BLOCKS   (GEMM_BLOCKS_X * 3)              // 1173
#define HIST_BLOCKS   ((E_EDGES / 4 + 255) / 256)      // 1563

// ---------------- scratch (static device globals: allowed) ----------------
__device__ __align__(16) __half g_Qh[N_NODES * OUT_DIM];
// interleaved K/V: per node 256 halfs; chunk j (j=0..31): [k4j..k4j+3, v4j..v4j+3]
__device__ __align__(16) __half g_KVh[N_NODES * OUT_DIM * 2];
__device__ int g_cnt[N_NODES];          // zero-init at load; re-zeroed by scan each call
__device__ int g_rowptr[N_NODES + 1];
__device__ int g_rank[E_EDGES];
__device__ int g_esrc[E_EDGES];

// ---------------- tensor-core GEMM helpers ----------------
#define GK 64                 // k-half width
#define AS_LD 72              // (GK+8) halfs per A row
#define WS_LD 136             // (128+8) halfs per W row

__device__ __forceinline__ void ldsm_x4(unsigned& r0, unsigned& r1, unsigned& r2, unsigned& r3,
                                        const __half* p) {
    unsigned addr = (unsigned)__cvta_generic_to_shared(p);
    asm volatile("ldmatrix.sync.aligned.m8n8.x4.shared.b16 {%0,%1,%2,%3}, [%4];"
                 : "=r"(r0), "=r"(r1), "=r"(r2), "=r"(r3) : "r"(addr));
}
__device__ __forceinline__ void ldsm_x4_t(unsigned& r0, unsigned& r1, unsigned& r2, unsigned& r3,
                                          const __half* p) {
    unsigned addr = (unsigned)__cvta_generic_to_shared(p);
    asm volatile("ldmatrix.sync.aligned.m8n8.x4.trans.shared.b16 {%0,%1,%2,%3}, [%4];"
                 : "=r"(r0), "=r"(r1), "=r"(r2), "=r"(r3) : "r"(addr));
}
__device__ __forceinline__ void mma16816(float* c, const unsigned* a, const unsigned* b) {
    asm volatile(
        "mma.sync.aligned.m16n8k16.row.col.f32.f16.f16.f32 "
        "{%0,%1,%2,%3}, {%4,%5,%6,%7}, {%8,%9}, {%0,%1,%2,%3};"
        : "+f"(c[0]), "+f"(c[1]), "+f"(c[2]), "+f"(c[3])
        : "r"(a[0]), "r"(a[1]), "r"(a[2]), "r"(a[3]), "r"(b[0]), "r"(b[1]));
}

// ---------------- fused: QKV GEMM (blocks [0,GEMM_BLOCKS)) + hist (rest) ----
__global__ __launch_bounds__(256) void gemm_hist_kernel(
    const float* __restrict__ hin,
    const float* __restrict__ WQ, const float* __restrict__ WK, const float* __restrict__ WV,
    const float* __restrict__ bQ, const float* __restrict__ bK, const float* __restrict__ bV,
    const int* __restrict__ dst)
{
    __shared__ __half As[128 * AS_LD];
    __shared__ __half Ws[GK * WS_LD];

    const int t = threadIdx.x;

    if (blockIdx.x >= GEMM_BLOCKS) {
        // ---- histogram branch: 4 edges/thread, record rank ----
        int i = (blockIdx.x - GEMM_BLOCKS) * 256 + t;
        if (i < E_EDGES / 4) {
            int4 d = reinterpret_cast<const int4*>(dst)[i];
            int r0 = atomicAdd(&g_cnt[d.x], 1);
            int r1 = atomicAdd(&g_cnt[d.y], 1);
            int r2 = atomicAdd(&g_cnt[d.z], 1);
            int r3 = atomicAdd(&g_cnt[d.w], 1);
            reinterpret_cast<int4*>(g_rank)[i] = make_int4(r0, r1, r2, r3);
        }
        return;
    }

    // ---- GEMM branch ----
    const int bx = blockIdx.x % GEMM_BLOCKS_X;
    const int by = blockIdx.x / GEMM_BLOCKS_X;

    const float* W;
    const float* bias;
    if (by == 0)      { W = WQ; bias = bQ; }
    else if (by == 1) { W = WK; bias = bK; }
    else              { W = WV; bias = bV; }

    const int lane   = t & 31;
    const int wid    = t >> 5;
    const int warp_m = wid >> 1;
    const int warp_n = wid & 1;
    const int row0   = bx * 128;

    float acc[2][8][4];
#pragma unroll
    for (int i = 0; i < 2; i++)
#pragma unroll
        for (int j = 0; j < 8; j++)
#pragma unroll
            for (int c = 0; c < 4; c++) acc[i][j][c] = 0.f;

    for (int kt = 0; kt < IN_DIM; kt += GK) {
#pragma unroll
        for (int i = 0; i < 8; i++) {
            int idx = t + i * 256;
            int r   = idx >> 4;
            int c4  = idx & 15;
            int row = row0 + r;
            float4 v = make_float4(0.f, 0.f, 0.f, 0.f);
            if (row < N_NODES)
                v = *reinterpret_cast<const float4*>(&hin[(size_t)row * IN_DIM + kt + c4 * 4]);
            __half2 h0 = __floats2half2_rn(v.x, v.y);
            __half2 h1 = __floats2half2_rn(v.z, v.w);
            *reinterpret_cast<__half2*>(&As[r * AS_LD + c4 * 4])     = h0;
            *reinterpret_cast<__half2*>(&As[r * AS_LD + c4 * 4 + 2]) = h1;
        }
#pragma unroll
        for (int i = 0; i < 8; i++) {
            int idx = t + i * 256;
            int k   = idx >> 5;
            int c4  = idx & 31;
            float4 v = *reinterpret_cast<const float4*>(&W[(size_t)(kt + k) * OUT_DIM + c4 * 4]);
            __half2 h0 = __floats2half2_rn(v.x, v.y);
            __half2 h1 = __floats2half2_rn(v.z, v.w);
            *reinterpret_cast<__half2*>(&Ws[k * WS_LD + c4 * 4])     = h0;
            *reinterpret_cast<__half2*>(&Ws[k * WS_LD + c4 * 4 + 2]) = h1;
        }
        __syncthreads();

#pragma unroll
        for (int kk = 0; kk < GK; kk += 16) {
            unsigned a[2][4];
#pragma unroll
            for (int i = 0; i < 2; i++) {
                int r = warp_m * 32 + i * 16 + (lane & 15);
                int c = kk + 8 * (lane >> 4);
                ldsm_x4(a[i][0], a[i][1], a[i][2], a[i][3], &As[r * AS_LD + c]);
            }
            unsigned b[4][4];
#pragma unroll
            for (int j = 0; j < 4; j++) {
                int kr = kk + (lane & 15);
                int c  = warp_n * 64 + j * 16 + 8 * (lane >> 4);
                ldsm_x4_t(b[j][0], b[j][1], b[j][2], b[j][3], &Ws[kr * WS_LD + c]);
            }
#pragma unroll
            for (int i = 0; i < 2; i++)
#pragma unroll
                for (int j2 = 0; j2 < 8; j2++)
                    mma16816(acc[i][j2], a[i], &b[j2 >> 1][(j2 & 1) * 2]);
        }
        __syncthreads();
    }

    // epilogue: +bias, fp16; Q -> g_Qh; K/V -> interleaved g_KVh
    const int kv_off = (by == 2) ? 4 : 0;
#pragma unroll
    for (int i = 0; i < 2; i++) {
        int row_a = row0 + warp_m * 32 + i * 16 + (lane >> 2);
        int row_b = row_a + 8;
#pragma unroll
        for (int j2 = 0; j2 < 8; j2++) {
            int col = warp_n * 64 + j2 * 8 + (lane & 3) * 2;
            float b0 = __ldg(&bias[col]);
            float b1 = __ldg(&bias[col + 1]);
            __half2 oa = __floats2half2_rn(acc[i][j2][0] + b0, acc[i][j2][1] + b1);
            __half2 ob = __floats2half2_rn(acc[i][j2][2] + b0, acc[i][j2][3] + b1);
            if (by == 0) {
                if (row_a < N_NODES)
                    *reinterpret_cast<__half2*>(&g_Qh[(size_t)row_a * OUT_DIM + col]) = oa;
                if (row_b < N_NODES)
                    *reinterpret_cast<__half2*>(&g_Qh[(size_t)row_b * OUT_DIM + col]) = ob;
            } else {
                size_t off = (size_t)(col >> 2) * 8 + kv_off + (col & 3);
                if (row_a < N_NODES)
                    *reinterpret_cast<__half2*>(&g_KVh[(size_t)row_a * OUT_DIM * 2 + off]) = oa;
                if (row_b < N_NODES)
                    *reinterpret_cast<__half2*>(&g_KVh[(size_t)row_b * OUT_DIM * 2 + off]) = ob;
            }
        }
    }
}

// ---------------- scan (rowptr; also re-zeroes g_cnt for next call) --------
__global__ __launch_bounds__(1024) void scan_kernel() {
    __shared__ int sums[1024];
    const int CH = 52;                       // 1024*52 >= 50000, 52 % 4 == 0
    const int t = threadIdx.x;
    const int base = t * CH;
    int s = 0;
    for (int i = 0; i < CH; i += 4) {
        int idx = base + i;
        if (idx + 3 < N_NODES) {
            int4 c = *reinterpret_cast<const int4*>(&g_cnt[idx]);
            s += c.x + c.y + c.z + c.w;
        } else {
            for (int j = 0; j < 4; j++)
                if (idx + j < N_NODES) s += g_cnt[idx + j];
        }
    }
    sums[t] = s;
    __syncthreads();
    for (int off = 1; off < 1024; off <<= 1) {
        int v = (t >= off) ? sums[t - off] : 0;
        __syncthreads();
        sums[t] += v;
        __syncthreads();
    }
    int run = sums[t] - s;
    for (int i = 0; i < CH; i++) {
        int idx = base + i;
        if (idx < N_NODES) {
            int c = g_cnt[idx];
            g_rowptr[idx] = run;
            run += c;
            g_cnt[idx] = 0;          // fold zero_cnt into the last reader
        }
    }
    if (t == 0) g_rowptr[N_NODES] = E_EDGES;
}

// ---------------- atomic-free scatter using precomputed ranks (4/thread) ----
__global__ void scatter_kernel(const int* __restrict__ src, const int* __restrict__ dst) {
    int i = blockIdx.x * blockDim.x + threadIdx.x;   // < E/4
    if (i < E_EDGES / 4) {
        int4 d = reinterpret_cast<const int4*>(dst)[i];
        int4 s = reinterpret_cast<const int4*>(src)[i];
        int4 r = reinterpret_cast<const int4*>(g_rank)[i];
        g_esrc[__ldg(&g_rowptr[d.x]) + r.x] = s.x;
        g_esrc[__ldg(&g_rowptr[d.y]) + r.y] = s.y;
        g_esrc[__ldg(&g_rowptr[d.z]) + r.z] = s.z;
        g_esrc[__ldg(&g_rowptr[d.w]) + r.w] = s.w;
    }
}

// ---------------- gather: warp per dst node (R10 config: serial tail) -------
struct F4 { float x, y, z, w; };

__device__ __forceinline__ F4 cvt2(unsigned lo, unsigned hi) {
    __half2 h0 = *reinterpret_cast<__half2*>(&lo);
    __half2 h1 = *reinterpret_cast<__half2*>(&hi);
    float2 f0 = __half22float2(h0);
    float2 f1 = __half22float2(h1);
    F4 r; r.x = f0.x; r.y = f0.y; r.z = f1.x; r.w = f1.y;
    return r;
}

__device__ __forceinline__ float edge_score(const F4& kv, const F4& qv) {
    float p = kv.x * qv.x + kv.y * qv.y + kv.z * qv.z + kv.w * qv.w;
    p += __shfl_xor_sync(0xFFFFFFFFu, p, 1);
    p += __shfl_xor_sync(0xFFFFFFFFu, p, 2);
    return __expf(fminf(fmaxf(p * 0.25f, -5.f), 5.f));
}

__global__ __launch_bounds__(256) void gather_kernel(float* __restrict__ out) {
    const int node = (blockIdx.x * blockDim.x + threadIdx.x) >> 5;
    if (node >= N_NODES) return;
    const int lane = threadIdx.x & 31;

    const uint2 qraw = *reinterpret_cast<const uint2*>(&g_Qh[(size_t)node * OUT_DIM + lane * 4]);
    const F4 qv = cvt2(qraw.x, qraw.y);
    const int beg = __ldg(&g_rowptr[node]);
    const int end = __ldg(&g_rowptr[node + 1]);

    float ax = 0.f, ay = 0.f, az = 0.f, aw = 0.f, z = 0.f;

    int i = beg;
    for (; i + 7 < end; i += 8) {
        int s[8];
#pragma unroll
        for (int j = 0; j < 8; j++) s[j] = __ldg(&g_esrc[i + j]);
        uint4 kv[8];
#pragma unroll
        for (int j = 0; j < 8; j++)
            kv[j] = *reinterpret_cast<const uint4*>(&g_KVh[(size_t)s[j] * OUT_DIM * 2 + lane * 8]);
#pragma unroll
        for (int j = 0; j < 8; j++) {
            F4 k = cvt2(kv[j].x, kv[j].y);
            float sc = edge_score(k, qv);
            F4 v = cvt2(kv[j].z, kv[j].w);
            ax = fmaf(sc, v.x, ax); ay = fmaf(sc, v.y, ay);
            az = fmaf(sc, v.z, az); aw = fmaf(sc, v.w, aw);
            z += sc;
        }
    }
    for (; i < end; i++) {
        int s0 = __ldg(&g_esrc[i]);
        uint4 kv0 = *reinterpret_cast<const uint4*>(&g_KVh[(size_t)s0 * OUT_DIM * 2 + lane * 8]);
        F4 k0 = cvt2(kv0.x, kv0.y);
        F4 v0 = cvt2(kv0.z, kv0.w);
        float sc0 = edge_score(k0, qv);
        ax = fmaf(sc0, v0.x, ax); ay = fmaf(sc0, v0.y, ay);
        az = fmaf(sc0, v0.z, az); aw = fmaf(sc0, v0.w, aw);
        z += sc0;
    }

    const float inv = 1.0f / z;
    float4 o = make_float4(ax * inv, ay * inv, az * inv, aw * inv);
    *reinterpret_cast<float4*>(&out[(size_t)node * OUT_DIM + lane * 4]) = o;
}

// ---------------- launch ----------------
extern "C" void kernel_launch(void* const* d_in, const int* in_sizes, int n_in,
                              void* d_out, int out_size)
{
    const float* h   = (const float*)d_in[0];
    const int*   src = (const int*)  d_in[1];
    const int*   dst = (const int*)  d_in[2];
    const float* WQ  = (const float*)d_in[3];
    const float* WK  = (const float*)d_in[4];
    const float* WV  = (const float*)d_in[5];
    const float* bQ  = (const float*)d_in[6];
    const float* bK  = (const float*)d_in[7];
    const float* bV  = (const float*)d_in[8];
    float* out = (float*)d_out;

    (void)in_sizes; (void)n_in; (void)out_size;

    // 1) fused QKV GEMM + histogram (g_cnt pre-zeroed by previous scan / static init)
    gemm_hist_kernel<<<GEMM_BLOCKS + HIST_BLOCKS, 256>>>(h, WQ, WK, WV, bQ, bK, bV, dst);

    // 2) rowptr scan (+ re-zero counts for next call)
    scan_kernel<<<1, 1024>>>();

    // 3) atomic-free scatter via ranks (4 edges/thread)
    scatter_kernel<<<(E_EDGES / 4 + 255) / 256, 256>>>(src, dst);

    // 4) warp-per-node gather + fused normalize
    gather_kernel<<<(N_NODES * 32 + 255) / 256, 256>>>(out);
}